// round 1
// baseline (speedup 1.0000x reference)
#include <cuda_runtime.h>
#include <math.h>

#define HT 128
#define WT 128
#define HS 256
#define WS 256
#define NC 32
#define NV 3
#define ND 48

// Scratch (no allocations allowed): channel-last features, cost volume, projections.
__device__ float d_featT[NV * HS * WS * NC];   // (v, y, x, c)  ~25MB
__device__ float d_cost[ND * HT * WT];         // (d, y, x)     ~3MB
__device__ float d_proj[NV * 12];              // 3x4 per view

// ---------------------------------------------------------------------------
// Kernel 1: tiny setup — proj_v = (Ks_v @ E_v[:3,:]) @ inv([Kt@Et[:3,:]; 0001])
// ---------------------------------------------------------------------------
__global__ void setup_kernel(const float* __restrict__ src_exts,  // (V,4,4)
                             const float* __restrict__ src_ints,  // (V,3,3)
                             const float* __restrict__ tar_exts,  // (1,4,4)
                             const float* __restrict__ tar_ints)  // (1,3,3)
{
    if (threadIdx.x != 0) return;
    double T[4][4], inv[4][4];
    // tar34 = Kt @ tar_exts[:3,:]
    for (int i = 0; i < 3; i++)
        for (int j = 0; j < 4; j++) {
            double s = 0.0;
            for (int k = 0; k < 3; k++)
                s += (double)tar_ints[i * 3 + k] * (double)tar_exts[k * 4 + j];
            T[i][j] = s;
        }
    T[3][0] = 0.0; T[3][1] = 0.0; T[3][2] = 0.0; T[3][3] = 1.0;
    for (int i = 0; i < 4; i++)
        for (int j = 0; j < 4; j++) inv[i][j] = (i == j) ? 1.0 : 0.0;
    // Gauss-Jordan with partial pivoting
    for (int col = 0; col < 4; col++) {
        int piv = col; double best = fabs(T[col][col]);
        for (int r = col + 1; r < 4; r++) {
            double a = fabs(T[r][col]);
            if (a > best) { best = a; piv = r; }
        }
        if (piv != col)
            for (int j = 0; j < 4; j++) {
                double t = T[col][j]; T[col][j] = T[piv][j]; T[piv][j] = t;
                t = inv[col][j]; inv[col][j] = inv[piv][j]; inv[piv][j] = t;
            }
        double p = 1.0 / T[col][col];
        for (int j = 0; j < 4; j++) { T[col][j] *= p; inv[col][j] *= p; }
        for (int r = 0; r < 4; r++)
            if (r != col) {
                double f = T[r][col];
                for (int j = 0; j < 4; j++) {
                    T[r][j] -= f * T[col][j];
                    inv[r][j] -= f * inv[col][j];
                }
            }
    }
    for (int v = 0; v < NV; v++) {
        const float* K = src_ints + v * 9;
        const float* E = src_exts + v * 16;
        double A[3][4];
        for (int i = 0; i < 3; i++)
            for (int j = 0; j < 4; j++) {
                double s = 0.0;
                for (int k = 0; k < 3; k++)
                    s += (double)K[i * 3 + k] * (double)E[k * 4 + j];
                A[i][j] = s;
            }
        for (int i = 0; i < 3; i++)
            for (int j = 0; j < 4; j++) {
                double s = 0.0;
                for (int k = 0; k < 4; k++) s += A[i][k] * inv[k][j];
                d_proj[v * 12 + i * 4 + j] = (float)s;
            }
    }
}

// ---------------------------------------------------------------------------
// Kernel 2: transpose (V,C,H,W) -> (V,H,W,C) so a bilinear tap is one 128B line
// ---------------------------------------------------------------------------
__global__ void transpose_kernel(const float* __restrict__ src)
{
    int idx = blockIdx.x * blockDim.x + threadIdx.x;  // v*HS*WS + y*WS + x
    if (idx >= NV * HS * WS) return;
    int x = idx & (WS - 1);
    int y = (idx >> 8) & (HS - 1);
    int v = idx >> 16;
    const float* in = src + ((size_t)(v * NC) * HS + y) * WS + x;
    float buf[NC];
#pragma unroll
    for (int c = 0; c < NC; c++) buf[c] = in[(size_t)c * HS * WS];
    float4* out = reinterpret_cast<float4*>(d_featT + (size_t)idx * NC);
#pragma unroll
    for (int c4 = 0; c4 < NC / 4; c4++)
        out[c4] = make_float4(buf[c4 * 4], buf[c4 * 4 + 1], buf[c4 * 4 + 2], buf[c4 * 4 + 3]);
}

// ---------------------------------------------------------------------------
// Kernel 3: cost volume. Warp = 4 pixels x 8 channel-groups (float4 each).
// cost(d,px) = (1/C)[ (1/V)ΣΣ w^2  -  (1/V^2) Σ_c (Σ_v w)^2 ]
// ---------------------------------------------------------------------------
__global__ void cost_kernel(const float* __restrict__ nearfar)
{
    const int lane = threadIdx.x;      // 0..31
    const int cg   = lane & 7;         // channel group (4 channels)
    const int pxl  = lane >> 3;        // 0..3
    const int x = blockIdx.x * 4 + pxl;
    const int y = blockIdx.y;
    const int d = blockIdx.z * 8 + threadIdx.y;
    const int pix = y * WT + x;

    const float nearv = nearfar[pix];
    const float farv  = nearfar[HT * WT + pix];
    const float depth = fmaf(farv - nearv, (float)d * (1.0f / (ND - 1)), nearv);
    const float X = (float)x + 0.5f;
    const float Y = (float)y + 0.5f;

    float4 s1 = make_float4(0.f, 0.f, 0.f, 0.f);
    float S2 = 0.f;

#pragma unroll
    for (int v = 0; v < NV; v++) {
        const float* P = d_proj + v * 12;
        float px_ = fmaf(fmaf(P[0], X, fmaf(P[1], Y, P[2])), depth, P[3]);
        float py_ = fmaf(fmaf(P[4], X, fmaf(P[5], Y, P[6])), depth, P[7]);
        float pz_ = fmaf(fmaf(P[8], X, fmaf(P[9], Y, P[10])), depth, P[11]);
        pz_ = fmaxf(pz_, 1e-6f);
        float gx = px_ / pz_ - 0.5f;
        float gy = py_ / pz_ - 0.5f;
        gx = fminf(fmaxf(gx, -1.0e6f), 1.0e6f);
        gy = fminf(fmaxf(gy, -1.0e6f), 1.0e6f);
        float x0f = floorf(gx), y0f = floorf(gy);
        float wx = gx - x0f, wy = gy - y0f;
        int x0 = (int)x0f, y0 = (int)y0f;
        int x1 = x0 + 1, y1 = y0 + 1;
        float w00 = (1.f - wy) * (1.f - wx);
        float w01 = (1.f - wy) * wx;
        float w10 = wy * (1.f - wx);
        float w11 = wy * wx;
        bool vx0 = (x0 >= 0) & (x0 < WS);
        bool vx1 = (x1 >= 0) & (x1 < WS);
        bool vy0 = (y0 >= 0) & (y0 < HS);
        bool vy1 = (y1 >= 0) & (y1 < HS);
        if (!(vy0 & vx0)) w00 = 0.f;
        if (!(vy0 & vx1)) w01 = 0.f;
        if (!(vy1 & vx0)) w10 = 0.f;
        if (!(vy1 & vx1)) w11 = 0.f;
        int cx0 = min(max(x0, 0), WS - 1);
        int cx1 = min(max(x1, 0), WS - 1);
        int cy0 = min(max(y0, 0), HS - 1);
        int cy1 = min(max(y1, 0), HS - 1);

        const float* base = d_featT + (size_t)v * HS * WS * NC + cg * 4;
        const float4 t00 = *reinterpret_cast<const float4*>(base + (size_t)(cy0 * WS + cx0) * NC);
        const float4 t01 = *reinterpret_cast<const float4*>(base + (size_t)(cy0 * WS + cx1) * NC);
        const float4 t10 = *reinterpret_cast<const float4*>(base + (size_t)(cy1 * WS + cx0) * NC);
        const float4 t11 = *reinterpret_cast<const float4*>(base + (size_t)(cy1 * WS + cx1) * NC);

        float4 w;
        w.x = w00 * t00.x + w01 * t01.x + w10 * t10.x + w11 * t11.x;
        w.y = w00 * t00.y + w01 * t01.y + w10 * t10.y + w11 * t11.y;
        w.z = w00 * t00.z + w01 * t01.z + w10 * t10.z + w11 * t11.z;
        w.w = w00 * t00.w + w01 * t01.w + w10 * t10.w + w11 * t11.w;

        s1.x += w.x; s1.y += w.y; s1.z += w.z; s1.w += w.w;
        S2 = fmaf(w.x, w.x, S2);
        S2 = fmaf(w.y, w.y, S2);
        S2 = fmaf(w.z, w.z, S2);
        S2 = fmaf(w.w, w.w, S2);
    }

    float q = s1.x * s1.x + s1.y * s1.y + s1.z * s1.z + s1.w * s1.w;
#pragma unroll
    for (int off = 1; off < 8; off <<= 1) {
        q  += __shfl_xor_sync(0xffffffffu, q, off);
        S2 += __shfl_xor_sync(0xffffffffu, S2, off);
    }
    if (cg == 0)
        d_cost[d * HT * WT + pix] = S2 * (1.0f / (NV * NC)) - q * (1.0f / (NV * NV * NC));
}

// ---------------------------------------------------------------------------
// Kernel 4: softmax over depth -> expected depth, CI
// ---------------------------------------------------------------------------
__global__ void depth_kernel(const float* __restrict__ nearfar, float* __restrict__ out)
{
    int pix = blockIdx.x * blockDim.x + threadIdx.x;
    if (pix >= HT * WT) return;
    const float nearv = nearfar[pix];
    const float farv  = nearfar[HT * WT + pix];
    const float step  = (farv - nearv) * (1.0f / (ND - 1));

    float c[ND];
    float m = -1e30f;
#pragma unroll
    for (int d = 0; d < ND; d++) {
        c[d] = -d_cost[d * HT * WT + pix];
        m = fmaxf(m, c[d]);
    }
    float Z = 0.f, S1 = 0.f;
#pragma unroll
    for (int d = 0; d < ND; d++) {
        float e = expf(c[d] - m);
        c[d] = e;  // reuse as exp
        Z += e;
        S1 = fmaf(e, fmaf(step, (float)d, nearv), S1);
    }
    const float invZ = 1.0f / Z;
    const float depth = S1 * invZ;
    float Svar = 0.f;
#pragma unroll
    for (int d = 0; d < ND; d++) {
        float dv = fmaf(step, (float)d, nearv);
        float diff = dv - depth;
        Svar = fmaf(c[d], diff * diff, Svar);
    }
    float var = Svar * invZ;
    float hc = sqrtf(fmaxf(var, 1e-12f));
    out[pix] = depth;                                   // depth (1,1,Ht,Wt)
    out[HT * WT + pix] = fmaxf(depth - hc, nearv);      // ci lower
    out[2 * HT * WT + pix] = fminf(depth + hc, farv);   // ci upper
}

// ---------------------------------------------------------------------------
extern "C" void kernel_launch(void* const* d_in, const int* in_sizes, int n_in,
                              void* d_out, int out_size)
{
    const float* src_feat = (const float*)d_in[0];
    const float* src_exts = (const float*)d_in[1];
    const float* src_ints = (const float*)d_in[2];
    const float* tar_exts = (const float*)d_in[3];
    const float* tar_ints = (const float*)d_in[4];
    const float* near_far = (const float*)d_in[5];
    (void)in_sizes; (void)n_in; (void)out_size;

    setup_kernel<<<1, 32>>>(src_exts, src_ints, tar_exts, tar_ints);

    transpose_kernel<<<(NV * HS * WS + 255) / 256, 256>>>(src_feat);

    dim3 cb(32, 8);
    dim3 cg(WT / 4, HT, ND / 8);
    cost_kernel<<<cg, cb>>>(near_far);

    depth_kernel<<<(HT * WT + 127) / 128, 128>>>(near_far, (float*)d_out);
}